// round 1
// baseline (speedup 1.0000x reference)
#include <cuda_runtime.h>

#define BATCH 8
#define NTOK  1024
#define DDIM  64
#define NF    11
#define NEG_INF_F (-1000000000.0f)

#define WARPS 8
#define RPW   2                       // rows per warp
#define ROWS_PER_BLOCK (WARPS * RPW)  // 16
#define THREADS 256

__global__ __launch_bounds__(THREADS, 2)
void featsim_kernel(const float* __restrict__ x,
                    const int*   __restrict__ xlen,
                    const float* __restrict__ fi,
                    float*       __restrict__ out)
{
    __shared__ float sfeat[NTOK * NF];   // 44 KB: features laid out [j][f], stride 11 (coprime w/ 32 banks)

    const int tid  = threadIdx.x;
    const int wid  = tid >> 5;
    const int lane = tid & 31;

    const int blocks_per_batch = NTOK / ROWS_PER_BLOCK;   // 64
    const int b  = blockIdx.x / blocks_per_batch;
    const int i0 = (blockIdx.x % blocks_per_batch) * ROWS_PER_BLOCK;

    const float* xb = x + (size_t)b * NTOK * DDIM;

    // Stage the 11 feature columns of this batch into shared.
    for (int idx = tid; idx < NTOK * NF; idx += THREADS) {
        int j = idx / NF;
        int f = idx - j * NF;
        sfeat[idx] = xb[j * DDIM + f];
    }
    __syncthreads();

    const int len = xlen[b];

    float w[NF];
#pragma unroll
    for (int f = 0; f < NF; f++) w[f] = fi[f];

    // This warp's row features (broadcast LDS -> registers).
    float ifeat[RPW][NF];
#pragma unroll
    for (int r = 0; r < RPW; r++) {
        int i = i0 + wid * RPW + r;
#pragma unroll
        for (int f = 0; f < NF; f++) ifeat[r][f] = sfeat[i * NF + f];
    }

    // Full row of 1024 attn values lives in registers: 32 chunks x 32 lanes.
    float acc[RPW][32];

#pragma unroll
    for (int c = 0; c < 32; c++) {
        const int j = c * 32 + lane;
        float jf[NF];
#pragma unroll
        for (int f = 0; f < NF; f++) jf[f] = sfeat[j * NF + f];  // conflict-free: stride 11
        const bool valid = (j < len);
#pragma unroll
        for (int r = 0; r < RPW; r++) {
            float v = 0.0f;
#pragma unroll
            for (int f = 0; f < NF; f++)
                v += w[f] * fabsf(ifeat[r][f] - jf[f]);
            // attn = -v if v < 1 else 0 ; invalid columns -> -1e9
            float m = (v < 1.0f) ? -v : 0.0f;
            acc[r][c] = valid ? m : NEG_INF_F;
        }
    }

    // Fused per-row softmax (row fully register-resident in this warp).
#pragma unroll
    for (int r = 0; r < RPW; r++) {
        float M = acc[r][0];
#pragma unroll
        for (int c = 1; c < 32; c++) M = fmaxf(M, acc[r][c]);
#pragma unroll
        for (int s = 16; s > 0; s >>= 1)
            M = fmaxf(M, __shfl_xor_sync(0xffffffffu, M, s));

        float S = 0.0f;
#pragma unroll
        for (int c = 0; c < 32; c++) {
            float e = __expf(acc[r][c] - M);   // exp(-1e9 - M) underflows to exactly 0
            acc[r][c] = e;
            S += e;
        }
#pragma unroll
        for (int s = 16; s > 0; s >>= 1)
            S += __shfl_xor_sync(0xffffffffu, S, s);

        const float inv = __fdividef(1.0f, S);

        const int i = i0 + wid * RPW + r;
        float* orow = out + ((size_t)b * NTOK + i) * NTOK;
#pragma unroll
        for (int c = 0; c < 32; c++)
            orow[c * 32 + lane] = acc[r][c] * inv;
    }
}

extern "C" void kernel_launch(void* const* d_in, const int* in_sizes, int n_in,
                              void* d_out, int out_size)
{
    const float* x    = (const float*)d_in[0];
    const int*   xlen = (const int*)  d_in[1];
    const float* fi   = (const float*)d_in[2];
    float*       out  = (float*)d_out;

    dim3 grid(BATCH * NTOK / ROWS_PER_BLOCK);   // 512 blocks
    featsim_kernel<<<grid, THREADS>>>(x, xlen, fi, out);
}

// round 4
// speedup vs baseline: 1.3178x; 1.3178x over previous
#include <cuda_runtime.h>

#define BATCH 8
#define NTOK  1024
#define DDIM  64
#define NF    11
#define SROW  12                      // padded row stride (words): 48B, 16B-aligned
#define WARPS 4
#define RPW   2                       // rows per warp
#define ROWS_PER_BLOCK (WARPS * RPW)  // 8
#define THREADS (WARPS * 32)          // 128
#define BLOCKS_PER_BATCH (NTOK / ROWS_PER_BLOCK)  // 128

__global__ __launch_bounds__(THREADS, 4)
void featsim_kernel(const float* __restrict__ x,
                    const int*   __restrict__ xlen,
                    const float* __restrict__ fi,
                    float*       __restrict__ out)
{
    __shared__ float sfeat[NTOK * SROW];   // 48 KB (j-rows only, up to nstage)

    const int tid  = threadIdx.x;
    const int wid  = tid >> 5;
    const int lane = tid & 31;

    const int b  = blockIdx.x >> 7;             // /128
    const int i0 = (blockIdx.x & 127) * ROWS_PER_BLOCK;

    const int len     = xlen[b];
    const int nchunks = (len + 31) >> 5;        // j-chunks with any valid column
    const int nstage  = nchunks << 5;           // j-rows to stage into shared

    const float* xb = x + (size_t)b * NTOK * DDIM;

    // Stage features of the first nstage tokens: 3 float4 per token.
    {
        const float4* xb4 = (const float4*)xb;
        for (int idx = tid; idx < nstage * 3; idx += THREADS) {
            int j = idx / 3;
            int q = idx - j * 3;
            float4 v = xb4[j * 16 + q];
            *(float4*)&sfeat[j * SROW + q * 4] = v;
        }
    }

    float w[NF];
#pragma unroll
    for (int f = 0; f < NF; f++) w[f] = fi[f];

    // This warp's i-row features straight from global (broadcast LDG.128, L2-hot).
    // ALL rows i are computed (rows i >= len still need a full softmax —
    // the reference masks columns only).
    float ifeat[RPW][NF];
    const int ibase = i0 + wid * RPW;
#pragma unroll
    for (int r = 0; r < RPW; r++) {
        const float4* rp = (const float4*)(xb + (size_t)(ibase + r) * DDIM);
        float4 t0 = rp[0], t1 = rp[1], t2 = rp[2];
        ifeat[r][0]=t0.x; ifeat[r][1]=t0.y; ifeat[r][2]=t0.z; ifeat[r][3]=t0.w;
        ifeat[r][4]=t1.x; ifeat[r][5]=t1.y; ifeat[r][6]=t1.z; ifeat[r][7]=t1.w;
        ifeat[r][8]=t2.x; ifeat[r][9]=t2.y; ifeat[r][10]=t2.z;
    }

    __syncthreads();

    float acc[RPW][32];
    float S[RPW];
#pragma unroll
    for (int r = 0; r < RPW; r++) S[r] = 0.0f;

    // Softmax is shift-invariant -> use M=0 (exp args are O(1..10), no overflow).
#pragma unroll
    for (int c = 0; c < 32; c++) {
        if (c < nchunks) {                 // uniform branch; skips fully-masked chunks
            const int j = (c << 5) + lane;
            float4 j0 = *(const float4*)&sfeat[j * SROW];
            float4 j1 = *(const float4*)&sfeat[j * SROW + 4];
            float4 j2 = *(const float4*)&sfeat[j * SROW + 8];
            const bool jv = (j < len);
#pragma unroll
            for (int r = 0; r < RPW; r++) {
                float a0 = w[0]*fabsf(ifeat[r][0]-j0.x) + w[1]*fabsf(ifeat[r][1]-j0.y);
                float a1 = w[2]*fabsf(ifeat[r][2]-j0.z) + w[3]*fabsf(ifeat[r][3]-j0.w);
                float a2 = w[4]*fabsf(ifeat[r][4]-j1.x) + w[5]*fabsf(ifeat[r][5]-j1.y);
                float a3 = w[6]*fabsf(ifeat[r][6]-j1.z) + w[7]*fabsf(ifeat[r][7]-j1.w);
                float a4 = w[8]*fabsf(ifeat[r][8]-j2.x) + w[9]*fabsf(ifeat[r][9]-j2.y);
                float a5 = w[10]*fabsf(ifeat[r][10]-j2.z);
                float v  = ((a0 + a1) + (a2 + a3)) + (a4 + a5);
                float m  = (v < 1.0f) ? -v : 0.0f;   // attn value
                float e  = __expf(m);
                e = jv ? e : 0.0f;                   // exp(-1e9) -> exactly 0
                acc[r][c] = e;
                S[r] += e;
            }
        }
    }

#pragma unroll
    for (int r = 0; r < RPW; r++) {
#pragma unroll
        for (int s = 16; s > 0; s >>= 1)
            S[r] += __shfl_xor_sync(0xffffffffu, S[r], s);
    }

    // Writeback: normalized probs for computed chunks, zeros for skipped chunks.
#pragma unroll
    for (int r = 0; r < RPW; r++) {
        const int i = ibase + r;
        float* orow = out + ((size_t)b * NTOK + i) * NTOK;
        const float inv = __fdividef(1.0f, S[r]);    // len >= 1 -> S > 0
#pragma unroll
        for (int c = 0; c < 32; c++)
            orow[(c << 5) + lane] = (c < nchunks) ? acc[r][c] * inv : 0.0f;
    }
}

extern "C" void kernel_launch(void* const* d_in, const int* in_sizes, int n_in,
                              void* d_out, int out_size)
{
    const float* x    = (const float*)d_in[0];
    const int*   xlen = (const int*)  d_in[1];
    const float* fi   = (const float*)d_in[2];
    float*       out  = (float*)d_out;

    dim3 grid(BATCH * BLOCKS_PER_BATCH);   // 1024 blocks
    featsim_kernel<<<grid, THREADS>>>(x, xlen, fi, out);
}